// round 9
// baseline (speedup 1.0000x reference)
#include <cuda_runtime.h>
#include <cuda_bf16.h>
#include <cstdint>

// Problem constants
#define NN 10000
#define DD 128
#define NDSZ (NN * DD)

// Scratch (device globals; no allocations)
__device__ float g_qkvs[4 * NDSZ];   // Q, K, V, S  (all fp32)
__device__ float g_h[NDSZ];          // hidden after layer 0
__device__ int   g_rowptr[NN + 1];

// ===========================================================================
// row_ptr: edges sorted by src; rowptr[i] = first index with src[e] >= i
// ===========================================================================
__global__ void build_rowptr_kernel(const int* __restrict__ src, int E) {
    int i = blockIdx.x * blockDim.x + threadIdx.x;
    if (i > NN) return;
    int lo = 0, hi = E;
    while (lo < hi) {
        int mid = (lo + hi) >> 1;
        if (src[mid] < i) lo = mid + 1; else hi = mid;
    }
    g_rowptr[i] = lo;
}

// ===========================================================================
// TF32 helpers (mma.sync — portable PTX, works under compute_103)
// ===========================================================================
__device__ __forceinline__ uint32_t f2tf32(float x) {
    uint32_t r;
    asm("cvt.rna.tf32.f32 %0, %1;" : "=r"(r) : "f"(x));
    return r;
}

__device__ __forceinline__ void mma_tf32(float* c, const uint32_t* a, const uint32_t* b) {
    asm volatile(
        "mma.sync.aligned.m16n8k8.row.col.f32.tf32.tf32.f32 "
        "{%0,%1,%2,%3}, {%4,%5,%6,%7}, {%8,%9}, {%0,%1,%2,%3};"
        : "+f"(c[0]), "+f"(c[1]), "+f"(c[2]), "+f"(c[3])
        : "r"(a[0]), "r"(a[1]), "r"(a[2]), "r"(a[3]),
          "r"(b[0]), "r"(b[1]));
}

// ===========================================================================
// Projection GEMM via TF32x3 mma.sync: out = A @ W + bias for {Q,K,V,S}.
// A: [NN,128] fp32. W: [L,128,128] (in-dim major). M=10000, N=128, K=128.
// CTA: 256 thr = 8 warps (4 along M x 2 along N). Tile 128x128, K-chunk 16.
// Warp tile 32x64: 2 m16 frags x 8 n8 frags. 3 products per (mi,ni,k8):
//   hi*hi + lo*hi + hi*lo   (TF32x3, fp32-class accuracy)
// Smem strides chosen so fragment LDS hits 32 distinct banks:
//   A stride 20 (g*20+tg mod 32 all distinct), B stride 136 (k*8+n distinct).
// ===========================================================================
#define ASTRIDE 20
#define BSTRIDE 136

__global__ __launch_bounds__(256)
void gemm_tf32_kernel(const float* __restrict__ xin,
                      const float* __restrict__ Wq, const float* __restrict__ Wk,
                      const float* __restrict__ Wv, const float* __restrict__ Ws,
                      const float* __restrict__ bq, const float* __restrict__ bk,
                      const float* __restrict__ bv, const float* __restrict__ bs,
                      int layer, int use_gh) {
    __shared__ uint32_t sAh[128 * ASTRIDE];
    __shared__ uint32_t sAl[128 * ASTRIDE];
    __shared__ uint32_t sBh[16 * BSTRIDE];
    __shared__ uint32_t sBl[16 * BSTRIDE];

    const int tid  = threadIdx.x;
    const int wid  = tid >> 5;
    const int lane = tid & 31;
    const int g    = lane >> 2;    // group id 0..7
    const int tg   = lane & 3;     // thread in group 0..3
    const int warpM = wid & 3;     // 0..3 (32 rows each)
    const int warpN = wid >> 2;    // 0..1 (64 cols each)

    const int rowbase = blockIdx.x * 128;
    const int mtx = blockIdx.y;

    const float* A = use_gh ? g_h : xin;
    const float* W = (mtx == 0 ? Wq : mtx == 1 ? Wk : mtx == 2 ? Wv : Ws)
                     + (size_t)layer * DD * DD;
    const float* bias = (mtx == 0 ? bq : mtx == 1 ? bk : mtx == 2 ? bv : bs)
                        + layer * DD;

    float acc[2][8][4];
    #pragma unroll
    for (int mi = 0; mi < 2; ++mi)
        #pragma unroll
        for (int ni = 0; ni < 8; ++ni)
            #pragma unroll
            for (int r = 0; r < 4; ++r) acc[mi][ni][r] = 0.f;

    for (int k0 = 0; k0 < DD; k0 += 16) {
        // ---- stage A chunk 128x16 as tf32 hi/lo ----
        #pragma unroll
        for (int r = 0; r < 2; ++r) {
            int f = tid + r * 256;
            int row = f >> 2;
            int c4  = f & 3;
            int m = rowbase + row;
            float4 v = make_float4(0.f, 0.f, 0.f, 0.f);
            if (m < NN) v = *(const float4*)&A[(size_t)m * DD + k0 + c4 * 4];
            const float* vp = (const float*)&v;
            #pragma unroll
            for (int j = 0; j < 4; ++j) {
                uint32_t h = f2tf32(vp[j]);
                float lo = vp[j] - __uint_as_float(h);
                sAh[row * ASTRIDE + c4 * 4 + j] = h;
                sAl[row * ASTRIDE + c4 * 4 + j] = f2tf32(lo);
            }
        }
        // ---- stage B chunk 16x128 as tf32 hi/lo ----
        #pragma unroll
        for (int r = 0; r < 2; ++r) {
            int f = tid + r * 256;
            int kr = f >> 5;
            int c4 = f & 31;
            float4 v = *(const float4*)&W[(size_t)(k0 + kr) * DD + c4 * 4];
            const float* vp = (const float*)&v;
            #pragma unroll
            for (int j = 0; j < 4; ++j) {
                uint32_t h = f2tf32(vp[j]);
                float lo = vp[j] - __uint_as_float(h);
                sBh[kr * BSTRIDE + c4 * 4 + j] = h;
                sBl[kr * BSTRIDE + c4 * 4 + j] = f2tf32(lo);
            }
        }
        __syncthreads();

        // ---- 2 k8 steps ----
        #pragma unroll
        for (int ks = 0; ks < 2; ++ks) {
            int ko = ks * 8;
            uint32_t ah[2][4], al[2][4];
            #pragma unroll
            for (int mi = 0; mi < 2; ++mi) {
                int r0 = (warpM * 32 + mi * 16 + g) * ASTRIDE;
                ah[mi][0] = sAh[r0 + ko + tg];
                ah[mi][1] = sAh[r0 + 8 * ASTRIDE + ko + tg];
                ah[mi][2] = sAh[r0 + ko + tg + 4];
                ah[mi][3] = sAh[r0 + 8 * ASTRIDE + ko + tg + 4];
                al[mi][0] = sAl[r0 + ko + tg];
                al[mi][1] = sAl[r0 + 8 * ASTRIDE + ko + tg];
                al[mi][2] = sAl[r0 + ko + tg + 4];
                al[mi][3] = sAl[r0 + 8 * ASTRIDE + ko + tg + 4];
            }
            #pragma unroll
            for (int ni = 0; ni < 8; ++ni) {
                int n0 = warpN * 64 + ni * 8 + g;
                uint32_t bh[2], bl[2];
                bh[0] = sBh[(ko + tg) * BSTRIDE + n0];
                bh[1] = sBh[(ko + tg + 4) * BSTRIDE + n0];
                bl[0] = sBl[(ko + tg) * BSTRIDE + n0];
                bl[1] = sBl[(ko + tg + 4) * BSTRIDE + n0];
                #pragma unroll
                for (int mi = 0; mi < 2; ++mi) {
                    mma_tf32(acc[mi][ni], ah[mi], bh);
                    mma_tf32(acc[mi][ni], al[mi], bh);
                    mma_tf32(acc[mi][ni], ah[mi], bl);
                }
            }
        }
        __syncthreads();
    }

    // ---- epilogue: bias + store fp32 ----
    float* outb = g_qkvs + (size_t)mtx * NDSZ;
    #pragma unroll
    for (int mi = 0; mi < 2; ++mi) {
        int m0 = rowbase + warpM * 32 + mi * 16 + g;
        int m1 = m0 + 8;
        #pragma unroll
        for (int ni = 0; ni < 8; ++ni) {
            int n = warpN * 64 + ni * 8 + tg * 2;
            float2 b2 = *(const float2*)&bias[n];
            if (m0 < NN) {
                float2 o0 = make_float2(acc[mi][ni][0] + b2.x, acc[mi][ni][1] + b2.y);
                *(float2*)&outb[(size_t)m0 * DD + n] = o0;
            }
            if (m1 < NN) {
                float2 o1 = make_float2(acc[mi][ni][2] + b2.x, acc[mi][ni][3] + b2.y);
                *(float2*)&outb[(size_t)m1 * DD + n] = o1;
            }
        }
    }
}

// ===========================================================================
// Attention: one warp per destination node, TWO independent online-softmax
// streams (even/odd edges) merged at the end — halves the serial dependency
// chain. K/V fp32. Graph symmetric: incoming nbrs of i = dst[e] for
// e in rowptr[i]..rowptr[i+1]. Self loop guarantees >=1 edge.
// ===========================================================================
__global__ __launch_bounds__(256)
void attn_kernel(const float* __restrict__ xin,
                 const int* __restrict__ nbr,
                 float* __restrict__ outp, int mode) {
    int gwarp = (blockIdx.x * blockDim.x + threadIdx.x) >> 5;
    if (gwarp >= NN) return;
    const int lane = threadIdx.x & 31;
    const int i = gwarp;

    const float* Q = g_qkvs;
    const float* K = g_qkvs + NDSZ;
    const float* V = g_qkvs + 2 * NDSZ;
    const float* S = g_qkvs + 3 * NDSZ;
    const float* h = mode ? g_h : xin;

    float4 q4 = *(const float4*)&Q[(size_t)i * DD + lane * 4];
    q4.x *= 0.25f; q4.y *= 0.25f; q4.z *= 0.25f; q4.w *= 0.25f;

    float m0 = -1e30f, z0 = 0.f, m1 = -1e30f, z1 = 0.f;
    float4 a0 = make_float4(0.f, 0.f, 0.f, 0.f);
    float4 a1 = make_float4(0.f, 0.f, 0.f, 0.f);

    const int e0 = g_rowptr[i];
    const int e1 = g_rowptr[i + 1];

    int e = e0;
    int jA = nbr[e0];
    int jB = (e0 + 1 < e1) ? nbr[e0 + 1] : 0;

    while (e + 1 < e1) {
        int jA2 = (e + 2 < e1) ? nbr[e + 2] : 0;
        int jB2 = (e + 3 < e1) ? nbr[e + 3] : 0;

        float4 kA = *(const float4*)&K[(size_t)jA * DD + lane * 4];
        float4 vA = *(const float4*)&V[(size_t)jA * DD + lane * 4];
        float4 kB = *(const float4*)&K[(size_t)jB * DD + lane * 4];
        float4 vB = *(const float4*)&V[(size_t)jB * DD + lane * 4];

        float dA = q4.x * kA.x + q4.y * kA.y + q4.z * kA.z + q4.w * kA.w;
        float dB = q4.x * kB.x + q4.y * kB.y + q4.z * kB.z + q4.w * kB.w;
        dA += __shfl_xor_sync(0xFFFFFFFFu, dA, 1);
        dB += __shfl_xor_sync(0xFFFFFFFFu, dB, 1);
        dA += __shfl_xor_sync(0xFFFFFFFFu, dA, 2);
        dB += __shfl_xor_sync(0xFFFFFFFFu, dB, 2);

        float nm0 = fmaxf(m0, dA);
        float s0 = __expf(m0 - nm0);
        float p0 = __expf(dA - nm0);
        z0 = z0 * s0 + p0;
        a0.x = a0.x * s0 + p0 * vA.x;
        a0.y = a0.y * s0 + p0 * vA.y;
        a0.z = a0.z * s0 + p0 * vA.z;
        a0.w = a0.w * s0 + p0 * vA.w;
        m0 = nm0;

        float nm1 = fmaxf(m1, dB);
        float s1 = __expf(m1 - nm1);
        float p1 = __expf(dB - nm1);
        z1 = z1 * s1 + p1;
        a1.x = a1.x * s1 + p1 * vB.x;
        a1.y = a1.y * s1 + p1 * vB.y;
        a1.z = a1.z * s1 + p1 * vB.z;
        a1.w = a1.w * s1 + p1 * vB.w;
        m1 = nm1;

        jA = jA2; jB = jB2; e += 2;
    }
    if (e < e1) {   // leftover single edge -> stream 0
        float4 kA = *(const float4*)&K[(size_t)jA * DD + lane * 4];
        float4 vA = *(const float4*)&V[(size_t)jA * DD + lane * 4];
        float dA = q4.x * kA.x + q4.y * kA.y + q4.z * kA.z + q4.w * kA.w;
        dA += __shfl_xor_sync(0xFFFFFFFFu, dA, 1);
        dA += __shfl_xor_sync(0xFFFFFFFFu, dA, 2);
        float nm0 = fmaxf(m0, dA);
        float s0 = __expf(m0 - nm0);
        float p0 = __expf(dA - nm0);
        z0 = z0 * s0 + p0;
        a0.x = a0.x * s0 + p0 * vA.x;
        a0.y = a0.y * s0 + p0 * vA.y;
        a0.z = a0.z * s0 + p0 * vA.z;
        a0.w = a0.w * s0 + p0 * vA.w;
        m0 = nm0;
    }

    // merge streams (flash combine; stream1 may be empty: s1 -> 0)
    float M = fmaxf(m0, m1);
    float s0 = __expf(m0 - M);
    float s1 = __expf(m1 - M);
    float z = z0 * s0 + z1 * s1;
    float inv = 1.f / z;
    float4 acc;
    acc.x = a0.x * s0 + a1.x * s1;
    acc.y = a0.y * s0 + a1.y * s1;
    acc.z = a0.z * s0 + a1.z * s1;
    acc.w = a0.w * s0 + a1.w * s1;

    float4 h4 = *(const float4*)&h[(size_t)i * DD + lane * 4];
    float4 s4 = *(const float4*)&S[(size_t)i * DD + lane * 4];
    float4 o;
    o.x = acc.x * inv + h4.x + s4.x;
    o.y = acc.y * inv + h4.y + s4.y;
    o.z = acc.z * inv + h4.z + s4.z;
    o.w = acc.w * inv + h4.w + s4.w;

    if (mode == 0) {
        o.x = fmaxf(o.x, 0.f); o.y = fmaxf(o.y, 0.f);
        o.z = fmaxf(o.z, 0.f); o.w = fmaxf(o.w, 0.f);
        *(float4*)&g_h[(size_t)i * DD + lane * 4] = o;
    } else {
        *(float4*)&outp[(size_t)i * DD + lane * 4] = o;
    }
}

// ===========================================================================
// Launch — only kernel launches.
// Inputs: 0=x 1=Wq 2=bq 3=Wk 4=bk 5=Wv 6=bv 7=Ws 8=bs 9=attn_window[2,E] int32
// ===========================================================================
extern "C" void kernel_launch(void* const* d_in, const int* in_sizes, int n_in,
                              void* d_out, int out_size) {
    const float* x  = (const float*)d_in[0];
    const float* Wq = (const float*)d_in[1];
    const float* bq = (const float*)d_in[2];
    const float* Wk = (const float*)d_in[3];
    const float* bk = (const float*)d_in[4];
    const float* Wv = (const float*)d_in[5];
    const float* bv = (const float*)d_in[6];
    const float* Ws = (const float*)d_in[7];
    const float* bs = (const float*)d_in[8];
    const int*   aw = (const int*)d_in[9];
    const int E = in_sizes[9] / 2;
    const int* src = aw;
    const int* dst = aw + E;

    build_rowptr_kernel<<<(NN + 256) / 256, 256>>>(src, E);

    dim3 ggrid((NN + 127) / 128, 4);
    dim3 agrid((NN * 32 + 255) / 256);

    // Layer 0
    gemm_tf32_kernel<<<ggrid, 256>>>(x, Wq, Wk, Wv, Ws, bq, bk, bv, bs, 0, 0);
    attn_kernel<<<agrid, 256>>>(x, dst, nullptr, 0);

    // Layer 1
    gemm_tf32_kernel<<<ggrid, 256>>>(x, Wq, Wk, Wv, Ws, bq, bk, bv, bs, 1, 1);
    attn_kernel<<<agrid, 256>>>(nullptr, dst, (float*)d_out, 1);
}

// round 10
// speedup vs baseline: 1.2595x; 1.2595x over previous
#include <cuda_runtime.h>
#include <cuda_bf16.h>
#include <cuda_fp16.h>
#include <cstdint>

// Problem constants
#define NN 10000
#define DD 128
#define NDSZ (NN * DD)

// Scratch (device globals; no allocations)
__device__ float g_qkvs[2 * NDSZ];        // Q (fp32), S (fp32)
__device__ uint4 g_kv[NN * 32];           // packed fp16 K|V: per node 32 x 16B
__device__ float g_h[NDSZ];               // hidden after layer 0
__device__ int   g_rowptr[NN + 1];

// ===========================================================================
// row_ptr: edges sorted by src; rowptr[i] = first index with src[e] >= i
// ===========================================================================
__global__ void build_rowptr_kernel(const int* __restrict__ src, int E) {
    int i = blockIdx.x * blockDim.x + threadIdx.x;
    if (i > NN) return;
    int lo = 0, hi = E;
    while (lo < hi) {
        int mid = (lo + hi) >> 1;
        if (src[mid] < i) lo = mid + 1; else hi = mid;
    }
    g_rowptr[i] = lo;
}

// ===========================================================================
// TF32 helpers (portable mma.sync PTX — compiles under compute_103)
// ===========================================================================
__device__ __forceinline__ uint32_t f2tf32(float x) {
    uint32_t r;
    asm("cvt.rna.tf32.f32 %0, %1;" : "=r"(r) : "f"(x));
    return r;
}

__device__ __forceinline__ void mma_tf32(float* c, const uint32_t* a, const uint32_t* b) {
    asm volatile(
        "mma.sync.aligned.m16n8k8.row.col.f32.tf32.tf32.f32 "
        "{%0,%1,%2,%3}, {%4,%5,%6,%7}, {%8,%9}, {%0,%1,%2,%3};"
        : "+f"(c[0]), "+f"(c[1]), "+f"(c[2]), "+f"(c[3])
        : "r"(a[0]), "r"(a[1]), "r"(a[2]), "r"(a[3]),
          "r"(b[0]), "r"(b[1]));
}

// ===========================================================================
// Projection GEMM via TF32x3: out = A @ W + bias for {Q,K,V,S}.
// CTA tile 64x128, 8 warps (4M x 2N), warp tile 16x64. grid (157, 4).
// K-chunk 16, smem ~27.6KB. Q,S -> fp32 g_qkvs; K,V -> packed fp16 g_kv.
// ===========================================================================
#define ASTRIDE 20
#define BSTRIDE 136

__global__ __launch_bounds__(256)
void gemm_tf32_kernel(const float* __restrict__ xin,
                      const float* __restrict__ Wq, const float* __restrict__ Wk,
                      const float* __restrict__ Wv, const float* __restrict__ Ws,
                      const float* __restrict__ bq, const float* __restrict__ bk,
                      const float* __restrict__ bv, const float* __restrict__ bs,
                      int layer, int use_gh) {
    __shared__ uint32_t sAh[64 * ASTRIDE];
    __shared__ uint32_t sAl[64 * ASTRIDE];
    __shared__ uint32_t sBh[16 * BSTRIDE];
    __shared__ uint32_t sBl[16 * BSTRIDE];

    const int tid  = threadIdx.x;
    const int wid  = tid >> 5;
    const int lane = tid & 31;
    const int g    = lane >> 2;    // 0..7
    const int tg   = lane & 3;     // 0..3
    const int warpM = wid & 3;     // 0..3 (16 rows each)
    const int warpN = wid >> 2;    // 0..1 (64 cols each)

    const int rowbase = blockIdx.x * 64;
    const int mtx = blockIdx.y;

    const float* A = use_gh ? g_h : xin;
    const float* W = (mtx == 0 ? Wq : mtx == 1 ? Wk : mtx == 2 ? Wv : Ws)
                     + (size_t)layer * DD * DD;
    const float* bias = (mtx == 0 ? bq : mtx == 1 ? bk : mtx == 2 ? bv : bs)
                        + layer * DD;

    float acc[8][4];
    #pragma unroll
    for (int ni = 0; ni < 8; ++ni)
        #pragma unroll
        for (int r = 0; r < 4; ++r) acc[ni][r] = 0.f;

    for (int k0 = 0; k0 < DD; k0 += 16) {
        // ---- stage A chunk 64x16 (1 float4 per thread) ----
        {
            int row = tid >> 2;
            int c4  = tid & 3;
            int m = rowbase + row;
            float4 v = make_float4(0.f, 0.f, 0.f, 0.f);
            if (m < NN) v = *(const float4*)&A[(size_t)m * DD + k0 + c4 * 4];
            uint4 h, l;
            h.x = f2tf32(v.x); l.x = f2tf32(v.x - __uint_as_float(h.x));
            h.y = f2tf32(v.y); l.y = f2tf32(v.y - __uint_as_float(h.y));
            h.z = f2tf32(v.z); l.z = f2tf32(v.z - __uint_as_float(h.z));
            h.w = f2tf32(v.w); l.w = f2tf32(v.w - __uint_as_float(h.w));
            *(uint4*)&sAh[row * ASTRIDE + c4 * 4] = h;
            *(uint4*)&sAl[row * ASTRIDE + c4 * 4] = l;
        }
        // ---- stage B chunk 16x128 (2 float4 per thread) ----
        #pragma unroll
        for (int r = 0; r < 2; ++r) {
            int f = tid + r * 256;
            int kr = f >> 5;
            int c4 = f & 31;
            float4 v = *(const float4*)&W[(size_t)(k0 + kr) * DD + c4 * 4];
            uint4 h, l;
            h.x = f2tf32(v.x); l.x = f2tf32(v.x - __uint_as_float(h.x));
            h.y = f2tf32(v.y); l.y = f2tf32(v.y - __uint_as_float(h.y));
            h.z = f2tf32(v.z); l.z = f2tf32(v.z - __uint_as_float(h.z));
            h.w = f2tf32(v.w); l.w = f2tf32(v.w - __uint_as_float(h.w));
            *(uint4*)&sBh[kr * BSTRIDE + c4 * 4] = h;
            *(uint4*)&sBl[kr * BSTRIDE + c4 * 4] = l;
        }
        __syncthreads();

        #pragma unroll
        for (int ks = 0; ks < 2; ++ks) {
            int ko = ks * 8;
            uint32_t ah[4], al[4];
            int r0 = (warpM * 16 + g) * ASTRIDE;
            ah[0] = sAh[r0 + ko + tg];
            ah[1] = sAh[r0 + 8 * ASTRIDE + ko + tg];
            ah[2] = sAh[r0 + ko + tg + 4];
            ah[3] = sAh[r0 + 8 * ASTRIDE + ko + tg + 4];
            al[0] = sAl[r0 + ko + tg];
            al[1] = sAl[r0 + 8 * ASTRIDE + ko + tg];
            al[2] = sAl[r0 + ko + tg + 4];
            al[3] = sAl[r0 + 8 * ASTRIDE + ko + tg + 4];
            #pragma unroll
            for (int ni = 0; ni < 8; ++ni) {
                int n0 = warpN * 64 + ni * 8 + g;
                uint32_t bh[2], bl[2];
                bh[0] = sBh[(ko + tg) * BSTRIDE + n0];
                bh[1] = sBh[(ko + tg + 4) * BSTRIDE + n0];
                bl[0] = sBl[(ko + tg) * BSTRIDE + n0];
                bl[1] = sBl[(ko + tg + 4) * BSTRIDE + n0];
                mma_tf32(acc[ni], ah, bh);
                mma_tf32(acc[ni], al, bh);
                mma_tf32(acc[ni], ah, bl);
            }
        }
        __syncthreads();
    }

    // ---- epilogue ----
    int m0 = rowbase + warpM * 16 + g;
    int m1 = m0 + 8;
    #pragma unroll
    for (int ni = 0; ni < 8; ++ni) {
        int n = warpN * 64 + ni * 8 + tg * 2;
        float2 b2 = *(const float2*)&bias[n];
        float2 o0 = make_float2(acc[ni][0] + b2.x, acc[ni][1] + b2.y);
        float2 o1 = make_float2(acc[ni][2] + b2.x, acc[ni][3] + b2.y);
        if (mtx == 0 || mtx == 3) {
            float* outb = g_qkvs + (mtx == 0 ? 0 : NDSZ);
            if (m0 < NN) *(float2*)&outb[(size_t)m0 * DD + n] = o0;
            if (m1 < NN) *(float2*)&outb[(size_t)m1 * DD + n] = o1;
        } else {
            // packed fp16 K|V: node row = 512B; group (n>>2) at 16B;
            // K at +0, V at +8; within-section offset (n&3)*2.
            size_t sect = (size_t)(n >> 2) * 16 + (mtx == 2 ? 8 : 0) + (n & 3) * 2;
            if (m0 < NN)
                *(__half2*)((char*)g_kv + (size_t)m0 * 512 + sect) = __floats2half2_rn(o0.x, o0.y);
            if (m1 < NN)
                *(__half2*)((char*)g_kv + (size_t)m1 * 512 + sect) = __floats2half2_rn(o1.x, o1.y);
        }
    }
}

// ===========================================================================
// Attention: one warp per destination node; dual-stream online softmax;
// ONE LDG.128 per edge per lane (packed fp16 K|V). Q/S/h fp32.
// ===========================================================================
__device__ __forceinline__ void unpack_kv(uint4 kv, float4& k4, float4& v4) {
    float2 a = __half22float2(*(__half2*)&kv.x);
    float2 b = __half22float2(*(__half2*)&kv.y);
    float2 c = __half22float2(*(__half2*)&kv.z);
    float2 d = __half22float2(*(__half2*)&kv.w);
    k4 = make_float4(a.x, a.y, b.x, b.y);
    v4 = make_float4(c.x, c.y, d.x, d.y);
}

__global__ __launch_bounds__(256)
void attn_kernel(const float* __restrict__ xin,
                 const int* __restrict__ nbr,
                 float* __restrict__ outp, int mode) {
    int gwarp = (blockIdx.x * blockDim.x + threadIdx.x) >> 5;
    if (gwarp >= NN) return;
    const int lane = threadIdx.x & 31;
    const int i = gwarp;

    const float* Q = g_qkvs;
    const float* S = g_qkvs + NDSZ;
    const float* h = mode ? g_h : xin;

    float4 q4 = *(const float4*)&Q[(size_t)i * DD + lane * 4];
    q4.x *= 0.25f; q4.y *= 0.25f; q4.z *= 0.25f; q4.w *= 0.25f;

    float m0 = -1e30f, z0 = 0.f, m1 = -1e30f, z1 = 0.f;
    float4 a0 = make_float4(0.f, 0.f, 0.f, 0.f);
    float4 a1 = make_float4(0.f, 0.f, 0.f, 0.f);

    const int e0 = g_rowptr[i];
    const int e1 = g_rowptr[i + 1];

    int e = e0;
    int jA = nbr[e0];
    int jB = (e0 + 1 < e1) ? nbr[e0 + 1] : 0;

    while (e + 1 < e1) {
        int jA2 = (e + 2 < e1) ? nbr[e + 2] : 0;
        int jB2 = (e + 3 < e1) ? nbr[e + 3] : 0;

        uint4 kvA = g_kv[(size_t)jA * 32 + lane];
        uint4 kvB = g_kv[(size_t)jB * 32 + lane];
        float4 kA, vA, kB, vB;
        unpack_kv(kvA, kA, vA);
        unpack_kv(kvB, kB, vB);

        float dA = q4.x * kA.x + q4.y * kA.y + q4.z * kA.z + q4.w * kA.w;
        float dB = q4.x * kB.x + q4.y * kB.y + q4.z * kB.z + q4.w * kB.w;
        dA += __shfl_xor_sync(0xFFFFFFFFu, dA, 1);
        dB += __shfl_xor_sync(0xFFFFFFFFu, dB, 1);
        dA += __shfl_xor_sync(0xFFFFFFFFu, dA, 2);
        dB += __shfl_xor_sync(0xFFFFFFFFu, dB, 2);

        float nm0 = fmaxf(m0, dA);
        float s0 = __expf(m0 - nm0);
        float p0 = __expf(dA - nm0);
        z0 = z0 * s0 + p0;
        a0.x = a0.x * s0 + p0 * vA.x;
        a0.y = a0.y * s0 + p0 * vA.y;
        a0.z = a0.z * s0 + p0 * vA.z;
        a0.w = a0.w * s0 + p0 * vA.w;
        m0 = nm0;

        float nm1 = fmaxf(m1, dB);
        float s1 = __expf(m1 - nm1);
        float p1 = __expf(dB - nm1);
        z1 = z1 * s1 + p1;
        a1.x = a1.x * s1 + p1 * vB.x;
        a1.y = a1.y * s1 + p1 * vB.y;
        a1.z = a1.z * s1 + p1 * vB.z;
        a1.w = a1.w * s1 + p1 * vB.w;
        m1 = nm1;

        jA = jA2; jB = jB2; e += 2;
    }
    if (e < e1) {   // leftover single edge -> stream 0
        uint4 kvA = g_kv[(size_t)jA * 32 + lane];
        float4 kA, vA;
        unpack_kv(kvA, kA, vA);
        float dA = q4.x * kA.x + q4.y * kA.y + q4.z * kA.z + q4.w * kA.w;
        dA += __shfl_xor_sync(0xFFFFFFFFu, dA, 1);
        dA += __shfl_xor_sync(0xFFFFFFFFu, dA, 2);
        float nm0 = fmaxf(m0, dA);
        float s0 = __expf(m0 - nm0);
        float p0 = __expf(dA - nm0);
        z0 = z0 * s0 + p0;
        a0.x = a0.x * s0 + p0 * vA.x;
        a0.y = a0.y * s0 + p0 * vA.y;
        a0.z = a0.z * s0 + p0 * vA.z;
        a0.w = a0.w * s0 + p0 * vA.w;
        m0 = nm0;
    }

    // merge streams
    float M = fmaxf(m0, m1);
    float s0 = __expf(m0 - M);
    float s1 = __expf(m1 - M);
    float z = z0 * s0 + z1 * s1;
    float inv = 1.f / z;
    float4 acc;
    acc.x = a0.x * s0 + a1.x * s1;
    acc.y = a0.y * s0 + a1.y * s1;
    acc.z = a0.z * s0 + a1.z * s1;
    acc.w = a0.w * s0 + a1.w * s1;

    float4 h4 = *(const float4*)&h[(size_t)i * DD + lane * 4];
    float4 s4 = *(const float4*)&S[(size_t)i * DD + lane * 4];
    float4 o;
    o.x = acc.x * inv + h4.x + s4.x;
    o.y = acc.y * inv + h4.y + s4.y;
    o.z = acc.z * inv + h4.z + s4.z;
    o.w = acc.w * inv + h4.w + s4.w;

    if (mode == 0) {
        o.x = fmaxf(o.x, 0.f); o.y = fmaxf(o.y, 0.f);
        o.z = fmaxf(o.z, 0.f); o.w = fmaxf(o.w, 0.f);
        *(float4*)&g_h[(size_t)i * DD + lane * 4] = o;
    } else {
        *(float4*)&outp[(size_t)i * DD + lane * 4] = o;
    }
}

// ===========================================================================
// Launch — only kernel launches.
// Inputs: 0=x 1=Wq 2=bq 3=Wk 4=bk 5=Wv 6=bv 7=Ws 8=bs 9=attn_window[2,E] int32
// ===========================================================================
extern "C" void kernel_launch(void* const* d_in, const int* in_sizes, int n_in,
                              void* d_out, int out_size) {
    const float* x  = (const float*)d_in[0];
    const float* Wq = (const float*)d_in[1];
    const float* bq = (const float*)d_in[2];
    const float* Wk = (const float*)d_in[3];
    const float* bk = (const float*)d_in[4];
    const float* Wv = (const float*)d_in[5];
    const float* bv = (const float*)d_in[6];
    const float* Ws = (const float*)d_in[7];
    const float* bs = (const float*)d_in[8];
    const int*   aw = (const int*)d_in[9];
    const int E = in_sizes[9] / 2;
    const int* src = aw;
    const int* dst = aw + E;

    build_rowptr_kernel<<<(NN + 256) / 256, 256>>>(src, E);

    dim3 ggrid((NN + 63) / 64, 4);
    dim3 agrid((NN * 32 + 255) / 256);

    // Layer 0
    gemm_tf32_kernel<<<ggrid, 256>>>(x, Wq, Wk, Wv, Ws, bq, bk, bv, bs, 0, 0);
    attn_kernel<<<agrid, 256>>>(x, dst, nullptr, 0);

    // Layer 1
    gemm_tf32_kernel<<<ggrid, 256>>>(x, Wq, Wk, Wv, Ws, bq, bk, bv, bs, 1, 1);
    attn_kernel<<<agrid, 256>>>(nullptr, dst, (float*)d_out, 1);
}